// round 3
// baseline (speedup 1.0000x reference)
#include <cuda_runtime.h>
#include <math_constants.h>
#include <stdint.h>

// Shapes: X [16384, 512] fp32, E [8192, 512] fp32.
// Out: [qste 8388608, q 8388608, q_loss, e_loss, indices 16384] fp32.

#define N_ROWS 16384
#define DIM    512
#define K_CODES 8192
#define NELEM (N_ROWS * DIM)
#define CAND_CAP 512
#define MARGIN 1.6e-3f

#define BM 128
#define BN 128
#define BK 32
#define STAGES 3
#define SA 36                       // smem row stride (words)
#define A_STAGE (BM * SA)           // 4608 words
#define B_STAGE (BN * SA)
#define SMEM_WORDS (STAGES * (A_STAGE + B_STAGE))   // 27648 words = 110592 B

// Scratch (device globals; no allocation allowed)
__device__ float  g_xx[N_ROWS];
__device__ float  g_ee[K_CODES];
__device__ int    g_cnt[N_ROWS];
__device__ uint2  g_cand[N_ROWS * CAND_CAP];   // (approx d bits, col)
__device__ int    g_idx[N_ROWS];
__device__ double g_partial[N_ROWS];

// ---------------------------------------------------------------------------
// 1) Row norms: sequential fl(acc + fl(v*v)) order (load-bearing for fp32
//    tie cells), float4 loads for MLP. Also zero candidate counters.
// ---------------------------------------------------------------------------
__global__ void norms_kernel(const float* __restrict__ X, const float* __restrict__ E) {
    int i = blockIdx.x * blockDim.x + threadIdx.x;
    if (i < N_ROWS) {
        const float* p = X + (size_t)i * DIM;
        float acc = 0.0f;
        for (int j = 0; j < DIM; j += 4) {
            float4 v = *reinterpret_cast<const float4*>(p + j);
            acc = __fadd_rn(acc, __fmul_rn(v.x, v.x));
            acc = __fadd_rn(acc, __fmul_rn(v.y, v.y));
            acc = __fadd_rn(acc, __fmul_rn(v.z, v.z));
            acc = __fadd_rn(acc, __fmul_rn(v.w, v.w));
        }
        g_xx[i] = acc;
        g_cnt[i] = 0;
    } else if (i < N_ROWS + K_CODES) {
        int r = i - N_ROWS;
        const float* p = E + (size_t)r * DIM;
        float acc = 0.0f;
        for (int j = 0; j < DIM; j += 4) {
            float4 v = *reinterpret_cast<const float4*>(p + j);
            acc = __fadd_rn(acc, __fmul_rn(v.x, v.x));
            acc = __fadd_rn(acc, __fmul_rn(v.y, v.y));
            acc = __fadd_rn(acc, __fmul_rn(v.z, v.z));
            acc = __fadd_rn(acc, __fmul_rn(v.w, v.w));
        }
        g_ee[r] = acc;
    }
}

// ---------------------------------------------------------------------------
// 2) Pipelined TF32 tensor GEMM (cp.async, raw fp32 bits = tf32 truncation)
//    + per-row block min + margin candidate push.
// ---------------------------------------------------------------------------
__device__ __forceinline__ uint32_t smem_u32(const void* p) {
    return (uint32_t)__cvta_generic_to_shared(p);
}
__device__ __forceinline__ void cp16(uint32_t dst, const void* src) {
    asm volatile("cp.async.cg.shared.global [%0], [%1], 16;\n" :: "r"(dst), "l"(src));
}

__device__ __forceinline__ void mma8(float* c, const uint32_t* a, const uint32_t* b) {
    asm volatile(
        "mma.sync.aligned.m16n8k8.row.col.f32.tf32.tf32.f32 "
        "{%0,%1,%2,%3}, {%4,%5,%6,%7}, {%8,%9}, {%0,%1,%2,%3};"
        : "+f"(c[0]), "+f"(c[1]), "+f"(c[2]), "+f"(c[3])
        : "r"(a[0]), "r"(a[1]), "r"(a[2]), "r"(a[3]), "r"(b[0]), "r"(b[1]));
}

__global__ __launch_bounds__(256, 2) void gemm_select_kernel(
        const float* __restrict__ X, const float* __restrict__ E) {
    extern __shared__ float smem[];
    float* As = smem;                         // [STAGES][A_STAGE]
    float* Bs = smem + STAGES * A_STAGE;      // [STAGES][B_STAGE]
    __shared__ int   s_min[BM];
    __shared__ float s_xx[BM];
    __shared__ float s_ee[BN];

    int tid = threadIdx.x;
    int lane = tid & 31, wid = tid >> 5;
    int wm = wid >> 2, wn = wid & 3;          // 2 x 4 warp grid, warp tile 64x32
    int n0 = blockIdx.y * BM;
    int c0 = blockIdx.x * BN;

    if (tid < BM) { s_min[tid] = 0x7f7fffff; s_xx[tid] = g_xx[n0 + tid]; }
    if (tid < BN) s_ee[tid] = g_ee[c0 + tid];

    // cp.async roles: thread -> (row, half) ; each copies 64B of A and 64B of B
    int crow = tid >> 1;
    int chalf = (tid & 1) * 16;               // k offset in floats
    const float* gA = X + (size_t)(n0 + crow) * DIM + chalf;
    const float* gB = E + (size_t)(c0 + crow) * DIM + chalf;
    uint32_t sA = smem_u32(As + crow * SA + chalf);
    uint32_t sB = smem_u32(Bs + crow * SA + chalf);

    const int KT = DIM / BK;                  // 16

    // prologue: stages 0..STAGES-2
#pragma unroll
    for (int s = 0; s < STAGES - 1; ++s) {
        uint32_t da = sA + s * A_STAGE * 4;
        uint32_t db = sB + s * B_STAGE * 4;
        const float* pa = gA + s * BK;
        const float* pb = gB + s * BK;
#pragma unroll
        for (int q = 0; q < 4; ++q) {
            cp16(da + q * 16, pa + q * 4);
            cp16(db + q * 16, pb + q * 4);
        }
        asm volatile("cp.async.commit_group;\n");
    }

    float acc[4][4][4];
#pragma unroll
    for (int mt = 0; mt < 4; ++mt)
#pragma unroll
        for (int nt = 0; nt < 4; ++nt)
#pragma unroll
            for (int h = 0; h < 4; ++h) acc[mt][nt][h] = 0.0f;

    for (int kt = 0; kt < KT; ++kt) {
        // issue stage kt+STAGES-1
        int ki = kt + STAGES - 1;
        if (ki < KT) {
            int buf = ki % STAGES;
            uint32_t da = sA + buf * A_STAGE * 4;
            uint32_t db = sB + buf * B_STAGE * 4;
            const float* pa = gA + ki * BK;
            const float* pb = gB + ki * BK;
#pragma unroll
            for (int q = 0; q < 4; ++q) {
                cp16(da + q * 16, pa + q * 4);
                cp16(db + q * 16, pb + q * 4);
            }
        }
        asm volatile("cp.async.commit_group;\n");
        asm volatile("cp.async.wait_group %0;\n" :: "n"(STAGES - 2));
        __syncthreads();

        const uint32_t* Ab = reinterpret_cast<const uint32_t*>(As + (kt % STAGES) * A_STAGE);
        const uint32_t* Bb = reinterpret_cast<const uint32_t*>(Bs + (kt % STAGES) * B_STAGE);
#pragma unroll
        for (int k8 = 0; k8 < BK; k8 += 8) {
            uint32_t af[4][4], bf[4][2];
            int kb = k8 + (lane & 3);
#pragma unroll
            for (int mt = 0; mt < 4; ++mt) {
                int r = wm * 64 + mt * 16 + (lane >> 2);
                af[mt][0] = Ab[r * SA + kb];
                af[mt][1] = Ab[(r + 8) * SA + kb];
                af[mt][2] = Ab[r * SA + kb + 4];
                af[mt][3] = Ab[(r + 8) * SA + kb + 4];
            }
#pragma unroll
            for (int nt = 0; nt < 4; ++nt) {
                int c = wn * 32 + nt * 8 + (lane >> 2);
                bf[nt][0] = Bb[c * SA + kb];
                bf[nt][1] = Bb[c * SA + kb + 4];
            }
#pragma unroll
            for (int mt = 0; mt < 4; ++mt)
#pragma unroll
                for (int nt = 0; nt < 4; ++nt)
                    mma8(acc[mt][nt], af[mt], bf[nt]);
        }
        __syncthreads();   // buffer consumed before re-issue next iteration
    }

    // Epilogue: approx distances, per-row block min, margin push.
#pragma unroll
    for (int mt = 0; mt < 4; ++mt) {
#pragma unroll
        for (int rr = 0; rr < 2; ++rr) {
            int rowb = wm * 64 + mt * 16 + (lane >> 2) + 8 * rr;
            float xxv = s_xx[rowb];
            float dmin_t = CUDART_INF_F;
#pragma unroll
            for (int nt = 0; nt < 4; ++nt) {
#pragma unroll
                for (int cc = 0; cc < 2; ++cc) {
                    int h = rr * 2 + cc;
                    int colb = wn * 32 + nt * 8 + 2 * (lane & 3) + cc;
                    float d = (xxv + s_ee[colb]) - 2.0f * acc[mt][nt][h];
                    acc[mt][nt][h] = d;
                    dmin_t = fminf(dmin_t, d);
                }
            }
            atomicMin(&s_min[rowb], __float_as_int(dmin_t));  // distances > 0
        }
    }
    __syncthreads();
#pragma unroll
    for (int mt = 0; mt < 4; ++mt) {
#pragma unroll
        for (int rr = 0; rr < 2; ++rr) {
            int rowb = wm * 64 + mt * 16 + (lane >> 2) + 8 * rr;
            float thr = __int_as_float(s_min[rowb]) + MARGIN;
#pragma unroll
            for (int nt = 0; nt < 4; ++nt) {
#pragma unroll
                for (int cc = 0; cc < 2; ++cc) {
                    int h = rr * 2 + cc;
                    float d = acc[mt][nt][h];
                    if (d <= thr) {
                        int gr = n0 + rowb;
                        int gc = c0 + wn * 32 + nt * 8 + 2 * (lane & 3) + cc;
                        int slot = atomicAdd(&g_cnt[gr], 1);
                        if (slot < CAND_CAP)
                            g_cand[gr * CAND_CAP + slot] =
                                make_uint2(__float_as_uint(d), (unsigned)gc);
                    }
                }
            }
        }
    }
}

// ---------------------------------------------------------------------------
// 3) Refine: per row, global approx min over candidates, margin filter,
//    exact fp32 re-eval with reference rounding + lowest-index ties.
// ---------------------------------------------------------------------------
__global__ __launch_bounds__(256) void refine_kernel(
        const float* __restrict__ X, const float* __restrict__ E) {
    int row = blockIdx.x;
    int tid = threadIdx.x;
    int lane = tid & 31, wid = tid >> 5;

    __shared__ float s_red[8];
    __shared__ float s_dot[8];
    __shared__ int   s_fc[64];
    __shared__ int   s_m;
    __shared__ float s_bd;
    __shared__ int   s_bk;

    int n = g_cnt[row];
    if (n > CAND_CAP) n = CAND_CAP;
    if (tid == 0) s_m = 0;

    // global approx min over all candidates (chunks of 256)
    float m = CUDART_INF_F;
    for (int base = 0; base < n; base += 256) {
        int t = base + tid;
        if (t < n) m = fminf(m, __uint_as_float(g_cand[row * CAND_CAP + t].x));
    }
#pragma unroll
    for (int o = 16; o > 0; o >>= 1) m = fminf(m, __shfl_xor_sync(0xffffffffu, m, o));
    if (lane == 0) s_red[wid] = m;
    __syncthreads();
    if (tid == 0) {
        float mm = s_red[0];
#pragma unroll
        for (int w = 1; w < 8; ++w) mm = fminf(mm, s_red[w]);
        s_red[0] = mm;
    }
    __syncthreads();
    float thr = s_red[0] + MARGIN;
    for (int base = 0; base < n; base += 256) {
        int t = base + tid;
        if (t < n) {
            uint2 u = g_cand[row * CAND_CAP + t];
            if (__uint_as_float(u.x) <= thr) {
                int s = atomicAdd(&s_m, 1);
                if (s < 64) s_fc[s] = (int)u.y;
            }
        }
    }
    __syncthreads();
    int m2 = s_m < 64 ? s_m : 64;

    const float* xr = X + (size_t)row * DIM;
    for (int j = 0; j < m2; ++j) {
        int cc = s_fc[j];
        const float* er = E + (size_t)cc * DIM;
        float a = __fmaf_rn(xr[tid], er[tid], 0.0f);
        a = __fmaf_rn(xr[tid + 256], er[tid + 256], a);
#pragma unroll
        for (int o = 16; o > 0; o >>= 1) a += __shfl_xor_sync(0xffffffffu, a, o);
        if (lane == 0) s_dot[wid] = a;
        __syncthreads();
        if (tid == 0) {
            float dot = s_dot[0];
#pragma unroll
            for (int w = 1; w < 8; ++w) dot += s_dot[w];
            float de = __fadd_rn(__fadd_rn(g_xx[row], g_ee[cc]),
                                 __fmul_rn(-2.0f, dot));
            if (j == 0) { s_bd = de; s_bk = cc; }
            else if (de < s_bd || (de == s_bd && cc < s_bk)) { s_bd = de; s_bk = cc; }
        }
        __syncthreads();
    }
    if (tid == 0) g_idx[row] = s_bk;
}

// ---------------------------------------------------------------------------
// 4) Outputs: gather + STE + per-row double partials of (q-x)^2.
// ---------------------------------------------------------------------------
__global__ __launch_bounds__(128) void output_kernel(
        const float* __restrict__ X, const float* __restrict__ E,
        float* __restrict__ out,
        int off_qste, int off_q, int off_idx, long out_size) {
    int row = blockIdx.x;
    __shared__ double red[128];
    int idx = g_idx[row];

    if (threadIdx.x == 0 && off_idx >= 0) {
        long p = (long)off_idx + row;
        if (p < out_size) out[p] = (float)idx;
    }

    double acc = 0.0;
#pragma unroll
    for (int u = 0; u < 4; ++u) {
        int cdim = threadIdx.x + u * 128;
        float ev = E[(size_t)idx * DIM + cdim];
        float xv = X[(size_t)row * DIM + cdim];
        float diff = __fadd_rn(ev, -xv);
        float qs   = __fadd_rn(xv, diff);
        long el = (long)row * DIM + cdim;
        if (off_qste >= 0) { long p = off_qste + el; if (p < out_size) out[p] = qs; }
        if (off_q    >= 0) { long p = off_q    + el; if (p < out_size) out[p] = ev; }
        acc += (double)__fmul_rn(diff, diff);
    }
    red[threadIdx.x] = acc;
    __syncthreads();
    for (int s = 64; s > 0; s >>= 1) {
        if (threadIdx.x < s) red[threadIdx.x] += red[threadIdx.x + s];
        __syncthreads();
    }
    if (threadIdx.x == 0) g_partial[row] = red[0];
}

__global__ __launch_bounds__(512) void loss_kernel(
        float* __restrict__ out, int off_ql, int off_el, long out_size) {
    __shared__ double red[512];
    double a = 0.0;
    int base = threadIdx.x * 32;
    for (int j = 0; j < 32; ++j) a += g_partial[base + j];
    red[threadIdx.x] = a;
    __syncthreads();
    for (int s = 256; s > 0; s >>= 1) {
        if (threadIdx.x < s) red[threadIdx.x] += red[threadIdx.x + s];
        __syncthreads();
    }
    if (threadIdx.x == 0) {
        float l = (float)(red[0] / (double)NELEM);
        if (off_ql >= 0 && off_ql < out_size) out[off_ql] = l;
        if (off_el >= 0 && off_el < out_size) out[off_el] = l;
    }
}

// ---------------------------------------------------------------------------
extern "C" void kernel_launch(void* const* d_in, const int* in_sizes, int n_in,
                              void* d_out, int out_size) {
    const float* X = (const float*)d_in[0];
    const float* E = (const float*)d_in[1];
    float* out = (float*)d_out;

    int off_qste = -1, off_q = -1, off_ql = -1, off_el = -1, off_idx = -1;
    const int NE = NELEM;
    if (out_size >= 2 * NE + 2 + N_ROWS) {
        off_qste = 0; off_q = NE; off_ql = 2 * NE; off_el = 2 * NE + 1; off_idx = 2 * NE + 2;
    } else if (out_size == NE)          { off_qste = 0; }
    else if (out_size == 2 * NE)        { off_qste = 0; off_q = NE; }
    else if (out_size == 2 * NE + 2)    { off_qste = 0; off_q = NE; off_ql = 2 * NE; off_el = 2 * NE + 1; }
    else if (out_size == N_ROWS)        { off_idx = 0; }
    else {
        off_qste = 0; off_q = NE; off_ql = 2 * NE; off_el = 2 * NE + 1; off_idx = 2 * NE + 2;
    }
    long osz = (long)out_size;

    static const int smem_bytes = SMEM_WORDS * 4;   // 110592
    cudaFuncSetAttribute(gemm_select_kernel,
                         cudaFuncAttributeMaxDynamicSharedMemorySize, smem_bytes);

    norms_kernel<<<(N_ROWS + K_CODES + 255) / 256, 256>>>(X, E);

    dim3 grid(K_CODES / BN, N_ROWS / BM);   // 64 x 128
    gemm_select_kernel<<<grid, 256, smem_bytes>>>(X, E);

    refine_kernel<<<N_ROWS, 256>>>(X, E);
    output_kernel<<<N_ROWS, 128>>>(X, E, out, off_qste, off_q, off_idx, osz);
    loss_kernel<<<1, 512>>>(out, off_ql, off_el, osz);
}

// round 5
// speedup vs baseline: 1.0065x; 1.0065x over previous
#include <cuda_runtime.h>
#include <math_constants.h>
#include <stdint.h>

// Shapes: X [16384, 512] fp32, E [8192, 512] fp32.
// Out: [qste 8388608, q 8388608, q_loss, e_loss, indices 16384] fp32.

#define N_ROWS 16384
#define DIM    512
#define K_CODES 8192
#define NELEM (N_ROWS * DIM)
#define CAND_CAP 512
#define MARGIN 1.6e-3f

#define BM 128
#define BN 128
#define BK 32
#define KT (DIM / BK)               // 16
#define STAGES 2
#define SA 36                       // smem row stride (words)
#define A_STAGE (BM * SA)           // 4608 words
#define B_STAGE (BN * SA)
#define SMEM_WORDS (STAGES * (A_STAGE + B_STAGE))   // 18432 words = 73728 B

// Scratch (device globals; no allocation allowed)
__device__ float  g_xx[N_ROWS];
__device__ float  g_ee[K_CODES];
__device__ int    g_cnt[N_ROWS];
__device__ uint2  g_cand[N_ROWS * CAND_CAP];   // (approx d bits, col)
__device__ int    g_idx[N_ROWS];
__device__ double g_partial[N_ROWS];

// ---------------------------------------------------------------------------
// 1) Row norms: sequential fl(acc + fl(v*v)) order (load-bearing for fp32
//    tie cells), float4 loads. Also zero candidate counters.
// ---------------------------------------------------------------------------
__global__ void norms_kernel(const float* __restrict__ X, const float* __restrict__ E) {
    int i = blockIdx.x * blockDim.x + threadIdx.x;
    if (i < N_ROWS) {
        const float* p = X + (size_t)i * DIM;
        float acc = 0.0f;
        for (int j = 0; j < DIM; j += 4) {
            float4 v = *reinterpret_cast<const float4*>(p + j);
            acc = __fadd_rn(acc, __fmul_rn(v.x, v.x));
            acc = __fadd_rn(acc, __fmul_rn(v.y, v.y));
            acc = __fadd_rn(acc, __fmul_rn(v.z, v.z));
            acc = __fadd_rn(acc, __fmul_rn(v.w, v.w));
        }
        g_xx[i] = acc;
        g_cnt[i] = 0;
    } else if (i < N_ROWS + K_CODES) {
        int r = i - N_ROWS;
        const float* p = E + (size_t)r * DIM;
        float acc = 0.0f;
        for (int j = 0; j < DIM; j += 4) {
            float4 v = *reinterpret_cast<const float4*>(p + j);
            acc = __fadd_rn(acc, __fmul_rn(v.x, v.x));
            acc = __fadd_rn(acc, __fmul_rn(v.y, v.y));
            acc = __fadd_rn(acc, __fmul_rn(v.z, v.z));
            acc = __fadd_rn(acc, __fmul_rn(v.w, v.w));
        }
        g_ee[r] = acc;
    }
}

// ---------------------------------------------------------------------------
// 2) TF32 tensor GEMM, 2-stage cp.async double buffer, 2 CTAs/SM.
//    Raw fp32 bits into HMMA tf32 (top-19-bit truncation; margin covers it).
// ---------------------------------------------------------------------------
__device__ __forceinline__ uint32_t smem_u32(const void* p) {
    return (uint32_t)__cvta_generic_to_shared(p);
}
__device__ __forceinline__ void cp16(uint32_t dst, const void* src) {
    asm volatile("cp.async.cg.shared.global [%0], [%1], 16;\n" :: "r"(dst), "l"(src));
}
__device__ __forceinline__ void mma8(float* c, const uint32_t* a, const uint32_t* b) {
    asm volatile(
        "mma.sync.aligned.m16n8k8.row.col.f32.tf32.tf32.f32 "
        "{%0,%1,%2,%3}, {%4,%5,%6,%7}, {%8,%9}, {%0,%1,%2,%3};"
        : "+f"(c[0]), "+f"(c[1]), "+f"(c[2]), "+f"(c[3])
        : "r"(a[0]), "r"(a[1]), "r"(a[2]), "r"(a[3]), "r"(b[0]), "r"(b[1]));
}

__global__ __launch_bounds__(256, 2) void gemm_select_kernel(
        const float* __restrict__ X, const float* __restrict__ E) {
    extern __shared__ float smem[];
    float* As = smem;                         // [STAGES][A_STAGE]
    float* Bs = smem + STAGES * A_STAGE;      // [STAGES][B_STAGE]
    __shared__ int   s_min[BM];
    __shared__ float s_xx[BM];
    __shared__ float s_ee[BN];

    int tid = threadIdx.x;
    int lane = tid & 31, wid = tid >> 5;
    int wm = wid >> 2, wn = wid & 3;          // 2 x 4 warp grid, warp tile 64x32
    int n0 = blockIdx.y * BM;
    int c0 = blockIdx.x * BN;

    if (tid < BM) { s_min[tid] = 0x7f7fffff; s_xx[tid] = g_xx[n0 + tid]; }
    if (tid < BN) s_ee[tid] = g_ee[c0 + tid];

    // cp.async roles: thread -> (row, half); each copies 64B of A and 64B of B
    int crow = tid >> 1;
    int chalf = (tid & 1) * 16;               // k offset (floats)
    const float* gA = X + (size_t)(n0 + crow) * DIM + chalf;
    const float* gB = E + (size_t)(c0 + crow) * DIM + chalf;
    uint32_t sA = smem_u32(As + crow * SA + chalf);
    uint32_t sB = smem_u32(Bs + crow * SA + chalf);

    // prologue: stage 0
#pragma unroll
    for (int q = 0; q < 4; ++q) {
        cp16(sA + q * 16, gA + q * 4);
        cp16(sB + q * 16, gB + q * 4);
    }
    asm volatile("cp.async.commit_group;\n");

    float acc[4][4][4];
#pragma unroll
    for (int mt = 0; mt < 4; ++mt)
#pragma unroll
        for (int nt = 0; nt < 4; ++nt)
#pragma unroll
            for (int h = 0; h < 4; ++h) acc[mt][nt][h] = 0.0f;

    for (int kt = 0; kt < KT; ++kt) {
        if (kt + 1 < KT) {
            // issue next stage into the other buffer
            int buf = (kt + 1) & 1;
            uint32_t da = sA + buf * A_STAGE * 4;
            uint32_t db = sB + buf * B_STAGE * 4;
            const float* pa = gA + (kt + 1) * BK;
            const float* pb = gB + (kt + 1) * BK;
#pragma unroll
            for (int q = 0; q < 4; ++q) {
                cp16(da + q * 16, pa + q * 4);
                cp16(db + q * 16, pb + q * 4);
            }
            asm volatile("cp.async.commit_group;\n");
            asm volatile("cp.async.wait_group 1;\n");   // stage kt landed
        } else {
            asm volatile("cp.async.wait_group 0;\n");   // final stage landed
        }
        __syncthreads();

        const uint32_t* Ab = reinterpret_cast<const uint32_t*>(As + (kt & 1) * A_STAGE);
        const uint32_t* Bb = reinterpret_cast<const uint32_t*>(Bs + (kt & 1) * B_STAGE);
#pragma unroll
        for (int k8 = 0; k8 < BK; k8 += 8) {
            uint32_t af[4][4], bf[4][2];
            int kb = k8 + (lane & 3);
#pragma unroll
            for (int mt = 0; mt < 4; ++mt) {
                int r = wm * 64 + mt * 16 + (lane >> 2);
                af[mt][0] = Ab[r * SA + kb];
                af[mt][1] = Ab[(r + 8) * SA + kb];
                af[mt][2] = Ab[r * SA + kb + 4];
                af[mt][3] = Ab[(r + 8) * SA + kb + 4];
            }
#pragma unroll
            for (int nt = 0; nt < 4; ++nt) {
                int c = wn * 32 + nt * 8 + (lane >> 2);
                bf[nt][0] = Bb[c * SA + kb];
                bf[nt][1] = Bb[c * SA + kb + 4];
            }
#pragma unroll
            for (int mt = 0; mt < 4; ++mt)
#pragma unroll
                for (int nt = 0; nt < 4; ++nt)
                    mma8(acc[mt][nt], af[mt], bf[nt]);
        }
        __syncthreads();   // buffer consumed before next re-issue
    }

    // Epilogue: approx distances, per-row block min, margin push.
#pragma unroll
    for (int mt = 0; mt < 4; ++mt) {
#pragma unroll
        for (int rr = 0; rr < 2; ++rr) {
            int rowb = wm * 64 + mt * 16 + (lane >> 2) + 8 * rr;
            float xxv = s_xx[rowb];
            float dmin_t = CUDART_INF_F;
#pragma unroll
            for (int nt = 0; nt < 4; ++nt) {
#pragma unroll
                for (int cc = 0; cc < 2; ++cc) {
                    int h = rr * 2 + cc;
                    int colb = wn * 32 + nt * 8 + 2 * (lane & 3) + cc;
                    float d = (xxv + s_ee[colb]) - 2.0f * acc[mt][nt][h];
                    acc[mt][nt][h] = d;
                    dmin_t = fminf(dmin_t, d);
                }
            }
            atomicMin(&s_min[rowb], __float_as_int(dmin_t));  // distances > 0
        }
    }
    __syncthreads();
#pragma unroll
    for (int mt = 0; mt < 4; ++mt) {
#pragma unroll
        for (int rr = 0; rr < 2; ++rr) {
            int rowb = wm * 64 + mt * 16 + (lane >> 2) + 8 * rr;
            float thr = __int_as_float(s_min[rowb]) + MARGIN;
#pragma unroll
            for (int nt = 0; nt < 4; ++nt) {
#pragma unroll
                for (int cc = 0; cc < 2; ++cc) {
                    int h = rr * 2 + cc;
                    float d = acc[mt][nt][h];
                    if (d <= thr) {
                        int gr = n0 + rowb;
                        int gc = c0 + wn * 32 + nt * 8 + 2 * (lane & 3) + cc;
                        int slot = atomicAdd(&g_cnt[gr], 1);
                        if (slot < CAND_CAP)
                            g_cand[gr * CAND_CAP + slot] =
                                make_uint2(__float_as_uint(d), (unsigned)gc);
                    }
                }
            }
        }
    }
}

// ---------------------------------------------------------------------------
// 3) Refine: global approx min over candidates, margin filter, exact fp32
//    re-eval with reference rounding + lowest-index ties.
// ---------------------------------------------------------------------------
__global__ __launch_bounds__(256) void refine_kernel(
        const float* __restrict__ X, const float* __restrict__ E) {
    int row = blockIdx.x;
    int tid = threadIdx.x;
    int lane = tid & 31, wid = tid >> 5;

    __shared__ float s_red[8];
    __shared__ float s_dot[8];
    __shared__ int   s_fc[64];
    __shared__ int   s_m;
    __shared__ float s_bd;
    __shared__ int   s_bk;

    int n = g_cnt[row];
    if (n > CAND_CAP) n = CAND_CAP;
    if (tid == 0) s_m = 0;

    float m = CUDART_INF_F;
    for (int base = 0; base < n; base += 256) {
        int t = base + tid;
        if (t < n) m = fminf(m, __uint_as_float(g_cand[row * CAND_CAP + t].x));
    }
#pragma unroll
    for (int o = 16; o > 0; o >>= 1) m = fminf(m, __shfl_xor_sync(0xffffffffu, m, o));
    if (lane == 0) s_red[wid] = m;
    __syncthreads();
    if (tid == 0) {
        float mm = s_red[0];
#pragma unroll
        for (int w = 1; w < 8; ++w) mm = fminf(mm, s_red[w]);
        s_red[0] = mm;
    }
    __syncthreads();
    float thr = s_red[0] + MARGIN;
    for (int base = 0; base < n; base += 256) {
        int t = base + tid;
        if (t < n) {
            uint2 u = g_cand[row * CAND_CAP + t];
            if (__uint_as_float(u.x) <= thr) {
                int s = atomicAdd(&s_m, 1);
                if (s < 64) s_fc[s] = (int)u.y;
            }
        }
    }
    __syncthreads();
    int m2 = s_m < 64 ? s_m : 64;

    const float* xr = X + (size_t)row * DIM;
    for (int j = 0; j < m2; ++j) {
        int cc = s_fc[j];
        const float* er = E + (size_t)cc * DIM;
        float a = __fmaf_rn(xr[tid], er[tid], 0.0f);
        a = __fmaf_rn(xr[tid + 256], er[tid + 256], a);
#pragma unroll
        for (int o = 16; o > 0; o >>= 1) a += __shfl_xor_sync(0xffffffffu, a, o);
        if (lane == 0) s_dot[wid] = a;
        __syncthreads();
        if (tid == 0) {
            float dot = s_dot[0];
#pragma unroll
            for (int w = 1; w < 8; ++w) dot += s_dot[w];
            float de = __fadd_rn(__fadd_rn(g_xx[row], g_ee[cc]),
                                 __fmul_rn(-2.0f, dot));
            if (j == 0) { s_bd = de; s_bk = cc; }
            else if (de < s_bd || (de == s_bd && cc < s_bk)) { s_bd = de; s_bk = cc; }
        }
        __syncthreads();
    }
    if (tid == 0) g_idx[row] = s_bk;
}

// ---------------------------------------------------------------------------
// 4) Outputs: gather + STE + per-row double partials of (q-x)^2.
// ---------------------------------------------------------------------------
__global__ __launch_bounds__(128) void output_kernel(
        const float* __restrict__ X, const float* __restrict__ E,
        float* __restrict__ out,
        int off_qste, int off_q, int off_idx, long out_size) {
    int row = blockIdx.x;
    __shared__ double red[128];
    int idx = g_idx[row];

    if (threadIdx.x == 0 && off_idx >= 0) {
        long p = (long)off_idx + row;
        if (p < out_size) out[p] = (float)idx;
    }

    double acc = 0.0;
#pragma unroll
    for (int u = 0; u < 4; ++u) {
        int cdim = threadIdx.x + u * 128;
        float ev = E[(size_t)idx * DIM + cdim];
        float xv = X[(size_t)row * DIM + cdim];
        float diff = __fadd_rn(ev, -xv);
        float qs   = __fadd_rn(xv, diff);
        long el = (long)row * DIM + cdim;
        if (off_qste >= 0) { long p = off_qste + el; if (p < out_size) out[p] = qs; }
        if (off_q    >= 0) { long p = off_q    + el; if (p < out_size) out[p] = ev; }
        acc += (double)__fmul_rn(diff, diff);
    }
    red[threadIdx.x] = acc;
    __syncthreads();
    for (int s = 64; s > 0; s >>= 1) {
        if (threadIdx.x < s) red[threadIdx.x] += red[threadIdx.x + s];
        __syncthreads();
    }
    if (threadIdx.x == 0) g_partial[row] = red[0];
}

__global__ __launch_bounds__(512) void loss_kernel(
        float* __restrict__ out, int off_ql, int off_el, long out_size) {
    __shared__ double red[512];
    double a = 0.0;
    int base = threadIdx.x * 32;
    for (int j = 0; j < 32; ++j) a += g_partial[base + j];
    red[threadIdx.x] = a;
    __syncthreads();
    for (int s = 256; s > 0; s >>= 1) {
        if (threadIdx.x < s) red[threadIdx.x] += red[threadIdx.x + s];
        __syncthreads();
    }
    if (threadIdx.x == 0) {
        float l = (float)(red[0] / (double)NELEM);
        if (off_ql >= 0 && off_ql < out_size) out[off_ql] = l;
        if (off_el >= 0 && off_el < out_size) out[off_el] = l;
    }
}

// ---------------------------------------------------------------------------
extern "C" void kernel_launch(void* const* d_in, const int* in_sizes, int n_in,
                              void* d_out, int out_size) {
    const float* X = (const float*)d_in[0];
    const float* E = (const float*)d_in[1];
    float* out = (float*)d_out;

    int off_qste = -1, off_q = -1, off_ql = -1, off_el = -1, off_idx = -1;
    const int NE = NELEM;
    if (out_size >= 2 * NE + 2 + N_ROWS) {
        off_qste = 0; off_q = NE; off_ql = 2 * NE; off_el = 2 * NE + 1; off_idx = 2 * NE + 2;
    } else if (out_size == NE)          { off_qste = 0; }
    else if (out_size == 2 * NE)        { off_qste = 0; off_q = NE; }
    else if (out_size == 2 * NE + 2)    { off_qste = 0; off_q = NE; off_ql = 2 * NE; off_el = 2 * NE + 1; }
    else if (out_size == N_ROWS)        { off_idx = 0; }
    else {
        off_qste = 0; off_q = NE; off_ql = 2 * NE; off_el = 2 * NE + 1; off_idx = 2 * NE + 2;
    }
    long osz = (long)out_size;

    static const int smem_bytes = SMEM_WORDS * 4;   // 73728
    cudaFuncSetAttribute(gemm_select_kernel,
                         cudaFuncAttributeMaxDynamicSharedMemorySize, smem_bytes);

    norms_kernel<<<(N_ROWS + K_CODES + 255) / 256, 256>>>(X, E);

    dim3 grid(K_CODES / BN, N_ROWS / BM);   // 64 x 128
    gemm_select_kernel<<<grid, 256, smem_bytes>>>(X, E);

    refine_kernel<<<N_ROWS, 256>>>(X, E);
    output_kernel<<<N_ROWS, 128>>>(X, E, out, off_qste, off_q, off_idx, osz);
    loss_kernel<<<1, 512>>>(out, off_ql, off_el, osz);
}

// round 6
// speedup vs baseline: 1.7572x; 1.7458x over previous
#include <cuda_runtime.h>
#include <cuda_fp16.h>
#include <math_constants.h>
#include <stdint.h>

// Shapes: X [16384, 512] fp32, E [8192, 512] fp32.
// Out: [qste 8388608, q 8388608, q_loss, e_loss, indices 16384] fp32.

#define N_ROWS 16384
#define DIM    512
#define K_CODES 8192
#define NELEM (N_ROWS * DIM)
#define CAND_CAP 512
#define MARGIN 1.6e-3f
#define DSCALE 0.000244140625f    // 2/8192 = 2^-12 (E pre-scaled by 8192)

#define BM 128
#define BN 128
#define BKH 64                    // k-chunk in halves
#define KT (DIM / BKH)            // 8
#define SAH 72                    // smem row stride in halves (144B: conflict-free)

// Scratch (device globals; no allocation allowed)
__device__ __align__(16) __half g_X16[NELEM];
__device__ __align__(16) __half g_E16[K_CODES * DIM];
__device__ float  g_xx[N_ROWS];
__device__ float  g_ee[K_CODES];
__device__ int    g_cnt[N_ROWS];
__device__ uint2  g_cand[N_ROWS * CAND_CAP];   // (approx d bits, col)
__device__ int    g_idx[N_ROWS];
__device__ double g_partial[N_ROWS];

// ---------------------------------------------------------------------------
// 1) Row norms: sequential fl(acc + fl(v*v)) order (load-bearing for fp32
//    tie cells). Also zero candidate counters.
// ---------------------------------------------------------------------------
__global__ void norms_kernel(const float* __restrict__ X, const float* __restrict__ E) {
    int i = blockIdx.x * blockDim.x + threadIdx.x;
    if (i < N_ROWS) {
        const float* p = X + (size_t)i * DIM;
        float acc = 0.0f;
        for (int j = 0; j < DIM; j += 4) {
            float4 v = *reinterpret_cast<const float4*>(p + j);
            acc = __fadd_rn(acc, __fmul_rn(v.x, v.x));
            acc = __fadd_rn(acc, __fmul_rn(v.y, v.y));
            acc = __fadd_rn(acc, __fmul_rn(v.z, v.z));
            acc = __fadd_rn(acc, __fmul_rn(v.w, v.w));
        }
        g_xx[i] = acc;
        g_cnt[i] = 0;
    } else if (i < N_ROWS + K_CODES) {
        int r = i - N_ROWS;
        const float* p = E + (size_t)r * DIM;
        float acc = 0.0f;
        for (int j = 0; j < DIM; j += 4) {
            float4 v = *reinterpret_cast<const float4*>(p + j);
            acc = __fadd_rn(acc, __fmul_rn(v.x, v.x));
            acc = __fadd_rn(acc, __fmul_rn(v.y, v.y));
            acc = __fadd_rn(acc, __fmul_rn(v.z, v.z));
            acc = __fadd_rn(acc, __fmul_rn(v.w, v.w));
        }
        g_ee[r] = acc;
    }
}

// ---------------------------------------------------------------------------
// 2) Convert X -> fp16, E*8192 -> fp16 (fully coalesced, 8 halves/thread).
// ---------------------------------------------------------------------------
__global__ void convert_kernel(const float* __restrict__ X, const float* __restrict__ E) {
    const int XCH = NELEM / 8;                 // 1048576
    const int ECH = K_CODES * DIM / 8;         // 524288
    int i = blockIdx.x * blockDim.x + threadIdx.x;
    if (i < XCH) {
        float4 a = *reinterpret_cast<const float4*>(X + i * 8);
        float4 b = *reinterpret_cast<const float4*>(X + i * 8 + 4);
        __half2 h[4];
        h[0] = __floats2half2_rn(a.x, a.y);
        h[1] = __floats2half2_rn(a.z, a.w);
        h[2] = __floats2half2_rn(b.x, b.y);
        h[3] = __floats2half2_rn(b.z, b.w);
        *reinterpret_cast<uint4*>(g_X16 + (size_t)i * 8) = *reinterpret_cast<uint4*>(h);
    } else if (i < XCH + ECH) {
        int j = i - XCH;
        float4 a = *reinterpret_cast<const float4*>(E + j * 8);
        float4 b = *reinterpret_cast<const float4*>(E + j * 8 + 4);
        __half2 h[4];
        h[0] = __floats2half2_rn(a.x * 8192.0f, a.y * 8192.0f);
        h[1] = __floats2half2_rn(a.z * 8192.0f, a.w * 8192.0f);
        h[2] = __floats2half2_rn(b.x * 8192.0f, b.y * 8192.0f);
        h[3] = __floats2half2_rn(b.z * 8192.0f, b.w * 8192.0f);
        *reinterpret_cast<uint4*>(g_E16 + (size_t)j * 8) = *reinterpret_cast<uint4*>(h);
    }
}

// ---------------------------------------------------------------------------
// 3) FP16 tensor GEMM (m16n8k16, fp32 accum), R2 scheduling structure:
//    LDG->STS->sync->compute, 2 CTAs/SM. Epilogue: min + margin push.
// ---------------------------------------------------------------------------
__device__ __forceinline__ void mma16(float* c, const uint32_t* a, const uint32_t* b) {
    asm volatile(
        "mma.sync.aligned.m16n8k16.row.col.f32.f16.f16.f32 "
        "{%0,%1,%2,%3}, {%4,%5,%6,%7}, {%8,%9}, {%0,%1,%2,%3};"
        : "+f"(c[0]), "+f"(c[1]), "+f"(c[2]), "+f"(c[3])
        : "r"(a[0]), "r"(a[1]), "r"(a[2]), "r"(a[3]), "r"(b[0]), "r"(b[1]));
}

__global__ __launch_bounds__(256, 2) void gemm_select_kernel() {
    __shared__ __half As[BM * SAH];
    __shared__ __half Bs[BN * SAH];
    __shared__ int   s_min[BM];
    __shared__ float s_xx[BM];
    __shared__ float s_ee[BN];

    int tid = threadIdx.x;
    int lane = tid & 31, wid = tid >> 5;
    int wm = wid >> 2, wn = wid & 3;          // 2 x 4 warp grid, warp tile 64x32
    int n0 = blockIdx.y * BM;
    int c0 = blockIdx.x * BN;

    if (tid < BM) { s_min[tid] = 0x7f7fffff; s_xx[tid] = g_xx[n0 + tid]; }
    if (tid < BN) s_ee[tid] = g_ee[c0 + tid];

    float acc[4][4][4];
#pragma unroll
    for (int mt = 0; mt < 4; ++mt)
#pragma unroll
        for (int nt = 0; nt < 4; ++nt)
#pragma unroll
            for (int h = 0; h < 4; ++h) acc[mt][nt][h] = 0.0f;

    // load roles: 1024 16B-chunks per matrix per k-tile; 4 per thread each.
    // chunk c: row = c>>3 (0..127), seg = c&7 (16B within the 128B row chunk)
    for (int kt = 0; kt < KT; ++kt) {
        __syncthreads();
#pragma unroll
        for (int i = 0; i < 4; ++i) {
            int c = tid + 256 * i;
            int row = c >> 3, seg = c & 7;
            uint4 va = *reinterpret_cast<const uint4*>(
                g_X16 + (size_t)(n0 + row) * DIM + kt * BKH + seg * 8);
            *reinterpret_cast<uint4*>(As + row * SAH + seg * 8) = va;
            uint4 vb = *reinterpret_cast<const uint4*>(
                g_E16 + (size_t)(c0 + row) * DIM + kt * BKH + seg * 8);
            *reinterpret_cast<uint4*>(Bs + row * SAH + seg * 8) = vb;
        }
        __syncthreads();

#pragma unroll
        for (int s = 0; s < 4; ++s) {          // 4 k16 steps per tile
            int kb = s * 16 + (lane & 3) * 2;
            uint32_t af[4][4], bf[4][2];
#pragma unroll
            for (int mt = 0; mt < 4; ++mt) {
                int r = wm * 64 + mt * 16 + (lane >> 2);
                af[mt][0] = *reinterpret_cast<const uint32_t*>(As + r * SAH + kb);
                af[mt][1] = *reinterpret_cast<const uint32_t*>(As + (r + 8) * SAH + kb);
                af[mt][2] = *reinterpret_cast<const uint32_t*>(As + r * SAH + kb + 8);
                af[mt][3] = *reinterpret_cast<const uint32_t*>(As + (r + 8) * SAH + kb + 8);
            }
#pragma unroll
            for (int nt = 0; nt < 4; ++nt) {
                int cc = wn * 32 + nt * 8 + (lane >> 2);
                bf[nt][0] = *reinterpret_cast<const uint32_t*>(Bs + cc * SAH + kb);
                bf[nt][1] = *reinterpret_cast<const uint32_t*>(Bs + cc * SAH + kb + 8);
            }
#pragma unroll
            for (int mt = 0; mt < 4; ++mt)
#pragma unroll
                for (int nt = 0; nt < 4; ++nt)
                    mma16(acc[mt][nt], af[mt], bf[nt]);
        }
    }

    // Epilogue: approx distances, per-row block min, margin push.
#pragma unroll
    for (int mt = 0; mt < 4; ++mt) {
#pragma unroll
        for (int rr = 0; rr < 2; ++rr) {
            int rowb = wm * 64 + mt * 16 + (lane >> 2) + 8 * rr;
            float xxv = s_xx[rowb];
            float dmin_t = CUDART_INF_F;
#pragma unroll
            for (int nt = 0; nt < 4; ++nt) {
#pragma unroll
                for (int cc = 0; cc < 2; ++cc) {
                    int h = rr * 2 + cc;
                    int colb = wn * 32 + nt * 8 + 2 * (lane & 3) + cc;
                    float d = (xxv + s_ee[colb]) - acc[mt][nt][h] * DSCALE;
                    acc[mt][nt][h] = d;
                    dmin_t = fminf(dmin_t, d);
                }
            }
            atomicMin(&s_min[rowb], __float_as_int(dmin_t));  // distances > 0
        }
    }
    __syncthreads();
#pragma unroll
    for (int mt = 0; mt < 4; ++mt) {
#pragma unroll
        for (int rr = 0; rr < 2; ++rr) {
            int rowb = wm * 64 + mt * 16 + (lane >> 2) + 8 * rr;
            float thr = __int_as_float(s_min[rowb]) + MARGIN;
#pragma unroll
            for (int nt = 0; nt < 4; ++nt) {
#pragma unroll
                for (int cc = 0; cc < 2; ++cc) {
                    int h = rr * 2 + cc;
                    float d = acc[mt][nt][h];
                    if (d <= thr) {
                        int gr = n0 + rowb;
                        int gc = c0 + wn * 32 + nt * 8 + 2 * (lane & 3) + cc;
                        int slot = atomicAdd(&g_cnt[gr], 1);
                        if (slot < CAND_CAP)
                            g_cand[gr * CAND_CAP + slot] =
                                make_uint2(__float_as_uint(d), (unsigned)gc);
                    }
                }
            }
        }
    }
}

// ---------------------------------------------------------------------------
// 4) Refine: global approx min over candidates, margin filter, exact fp32
//    re-eval with reference rounding + lowest-index ties.
// ---------------------------------------------------------------------------
__global__ __launch_bounds__(256) void refine_kernel(
        const float* __restrict__ X, const float* __restrict__ E) {
    int row = blockIdx.x;
    int tid = threadIdx.x;
    int lane = tid & 31, wid = tid >> 5;

    __shared__ float s_red[8];
    __shared__ float s_dot[8];
    __shared__ int   s_fc[64];
    __shared__ int   s_m;
    __shared__ float s_bd;
    __shared__ int   s_bk;

    int n = g_cnt[row];
    if (n > CAND_CAP) n = CAND_CAP;
    if (tid == 0) s_m = 0;

    float m = CUDART_INF_F;
    for (int base = 0; base < n; base += 256) {
        int t = base + tid;
        if (t < n) m = fminf(m, __uint_as_float(g_cand[row * CAND_CAP + t].x));
    }
#pragma unroll
    for (int o = 16; o > 0; o >>= 1) m = fminf(m, __shfl_xor_sync(0xffffffffu, m, o));
    if (lane == 0) s_red[wid] = m;
    __syncthreads();
    if (tid == 0) {
        float mm = s_red[0];
#pragma unroll
        for (int w = 1; w < 8; ++w) mm = fminf(mm, s_red[w]);
        s_red[0] = mm;
    }
    __syncthreads();
    float thr = s_red[0] + MARGIN;
    for (int base = 0; base < n; base += 256) {
        int t = base + tid;
        if (t < n) {
            uint2 u = g_cand[row * CAND_CAP + t];
            if (__uint_as_float(u.x) <= thr) {
                int s = atomicAdd(&s_m, 1);
                if (s < 64) s_fc[s] = (int)u.y;
            }
        }
    }
    __syncthreads();
    int m2 = s_m < 64 ? s_m : 64;

    const float* xr = X + (size_t)row * DIM;
    for (int j = 0; j < m2; ++j) {
        int cc = s_fc[j];
        const float* er = E + (size_t)cc * DIM;
        float a = __fmaf_rn(xr[tid], er[tid], 0.0f);
        a = __fmaf_rn(xr[tid + 256], er[tid + 256], a);
#pragma unroll
        for (int o = 16; o > 0; o >>= 1) a += __shfl_xor_sync(0xffffffffu, a, o);
        if (lane == 0) s_dot[wid] = a;
        __syncthreads();
        if (tid == 0) {
            float dot = s_dot[0];
#pragma unroll
            for (int w = 1; w < 8; ++w) dot += s_dot[w];
            float de = __fadd_rn(__fadd_rn(g_xx[row], g_ee[cc]),
                                 __fmul_rn(-2.0f, dot));
            if (j == 0) { s_bd = de; s_bk = cc; }
            else if (de < s_bd || (de == s_bd && cc < s_bk)) { s_bd = de; s_bk = cc; }
        }
        __syncthreads();
    }
    if (tid == 0) g_idx[row] = s_bk;
}

// ---------------------------------------------------------------------------
// 5) Outputs: gather + STE + per-row double partials of (q-x)^2.
// ---------------------------------------------------------------------------
__global__ __launch_bounds__(128) void output_kernel(
        const float* __restrict__ X, const float* __restrict__ E,
        float* __restrict__ out,
        int off_qste, int off_q, int off_idx, long out_size) {
    int row = blockIdx.x;
    __shared__ double red[128];
    int idx = g_idx[row];

    if (threadIdx.x == 0 && off_idx >= 0) {
        long p = (long)off_idx + row;
        if (p < out_size) out[p] = (float)idx;
    }

    double acc = 0.0;
#pragma unroll
    for (int u = 0; u < 4; ++u) {
        int cdim = threadIdx.x + u * 128;
        float ev = E[(size_t)idx * DIM + cdim];
        float xv = X[(size_t)row * DIM + cdim];
        float diff = __fadd_rn(ev, -xv);
        float qs   = __fadd_rn(xv, diff);
        long el = (long)row * DIM + cdim;
        if (off_qste >= 0) { long p = off_qste + el; if (p < out_size) out[p] = qs; }
        if (off_q    >= 0) { long p = off_q    + el; if (p < out_size) out[p] = ev; }
        acc += (double)__fmul_rn(diff, diff);
    }
    red[threadIdx.x] = acc;
    __syncthreads();
    for (int s = 64; s > 0; s >>= 1) {
        if (threadIdx.x < s) red[threadIdx.x] += red[threadIdx.x + s];
        __syncthreads();
    }
    if (threadIdx.x == 0) g_partial[row] = red[0];
}

__global__ __launch_bounds__(512) void loss_kernel(
        float* __restrict__ out, int off_ql, int off_el, long out_size) {
    __shared__ double red[512];
    double a = 0.0;
    int base = threadIdx.x * 32;
    for (int j = 0; j < 32; ++j) a += g_partial[base + j];
    red[threadIdx.x] = a;
    __syncthreads();
    for (int s = 256; s > 0; s >>= 1) {
        if (threadIdx.x < s) red[threadIdx.x] += red[threadIdx.x + s];
        __syncthreads();
    }
    if (threadIdx.x == 0) {
        float l = (float)(red[0] / (double)NELEM);
        if (off_ql >= 0 && off_ql < out_size) out[off_ql] = l;
        if (off_el >= 0 && off_el < out_size) out[off_el] = l;
    }
}

// ---------------------------------------------------------------------------
extern "C" void kernel_launch(void* const* d_in, const int* in_sizes, int n_in,
                              void* d_out, int out_size) {
    const float* X = (const float*)d_in[0];
    const float* E = (const float*)d_in[1];
    float* out = (float*)d_out;

    int off_qste = -1, off_q = -1, off_ql = -1, off_el = -1, off_idx = -1;
    const int NE = NELEM;
    if (out_size >= 2 * NE + 2 + N_ROWS) {
        off_qste = 0; off_q = NE; off_ql = 2 * NE; off_el = 2 * NE + 1; off_idx = 2 * NE + 2;
    } else if (out_size == NE)          { off_qste = 0; }
    else if (out_size == 2 * NE)        { off_qste = 0; off_q = NE; }
    else if (out_size == 2 * NE + 2)    { off_qste = 0; off_q = NE; off_ql = 2 * NE; off_el = 2 * NE + 1; }
    else if (out_size == N_ROWS)        { off_idx = 0; }
    else {
        off_qste = 0; off_q = NE; off_ql = 2 * NE; off_el = 2 * NE + 1; off_idx = 2 * NE + 2;
    }
    long osz = (long)out_size;

    norms_kernel<<<(N_ROWS + K_CODES + 255) / 256, 256>>>(X, E);
    convert_kernel<<<(NELEM / 8 + K_CODES * DIM / 8 + 255) / 256, 256>>>(X, E);

    dim3 grid(K_CODES / BN, N_ROWS / BM);   // 64 x 128
    gemm_select_kernel<<<grid, 256>>>();

    refine_kernel<<<N_ROWS, 256>>>(X, E);
    output_kernel<<<N_ROWS, 128>>>(X, E, out, off_qste, off_q, off_idx, osz);
    loss_kernel<<<1, 512>>>(out, off_ql, off_el, osz);
}

// round 8
// speedup vs baseline: 1.8689x; 1.0635x over previous
#include <cuda_runtime.h>
#include <cuda_fp16.h>
#include <math_constants.h>
#include <stdint.h>

// Shapes: X [16384, 512] fp32, E [8192, 512] fp32.
// Out: [qste 8388608, q 8388608, q_loss, e_loss, indices 16384] fp32.

#define N_ROWS 16384
#define DIM    512
#define K_CODES 8192
#define NELEM (N_ROWS * DIM)
#define CAND_CAP 512
#define MARGIN 1.6e-3f
#define DSCALE 0.000244140625f    // 2/8192 = 2^-12 (E pre-scaled by 8192)

#define BM 128
#define BN 128
#define BKH 64                    // k-chunk in halves
#define KT (DIM / BKH)            // 8
#define SAH 72                    // smem row stride in halves (144B)

// Scratch (device globals; no allocation allowed)
__device__ __align__(16) __half g_X16[NELEM];
__device__ __align__(16) __half g_E16[K_CODES * DIM];
__device__ float  g_xx[N_ROWS];
__device__ float  g_ee[K_CODES];
__device__ int    g_cnt[N_ROWS];
__device__ uint2  g_cand[N_ROWS * CAND_CAP];   // (approx d bits, col)
__device__ int    g_idx[N_ROWS];
__device__ double g_partial[N_ROWS];

// ---------------------------------------------------------------------------
// 1) Fused prep: fp16 convert (coalesced bulk) + row norms (sequential
//    reference order, load-bearing) + counter zeroing, one launch.
// ---------------------------------------------------------------------------
#define XCH (NELEM / 8)               // 1048576
#define ECH (K_CODES * DIM / 8)       // 524288
#define PREP_THREADS (XCH + ECH + N_ROWS + K_CODES)

__global__ void prep_kernel(const float* __restrict__ X, const float* __restrict__ E) {
    int i = blockIdx.x * blockDim.x + threadIdx.x;
    if (i < XCH) {
        float4 a = *reinterpret_cast<const float4*>(X + (size_t)i * 8);
        float4 b = *reinterpret_cast<const float4*>(X + (size_t)i * 8 + 4);
        __half2 h[4];
        h[0] = __floats2half2_rn(a.x, a.y);
        h[1] = __floats2half2_rn(a.z, a.w);
        h[2] = __floats2half2_rn(b.x, b.y);
        h[3] = __floats2half2_rn(b.z, b.w);
        *reinterpret_cast<uint4*>(g_X16 + (size_t)i * 8) = *reinterpret_cast<uint4*>(h);
    } else if (i < XCH + ECH) {
        int j = i - XCH;
        float4 a = *reinterpret_cast<const float4*>(E + (size_t)j * 8);
        float4 b = *reinterpret_cast<const float4*>(E + (size_t)j * 8 + 4);
        __half2 h[4];
        h[0] = __floats2half2_rn(a.x * 8192.0f, a.y * 8192.0f);
        h[1] = __floats2half2_rn(a.z * 8192.0f, a.w * 8192.0f);
        h[2] = __floats2half2_rn(b.x * 8192.0f, b.y * 8192.0f);
        h[3] = __floats2half2_rn(b.z * 8192.0f, b.w * 8192.0f);
        *reinterpret_cast<uint4*>(g_E16 + (size_t)j * 8) = *reinterpret_cast<uint4*>(h);
    } else if (i < XCH + ECH + N_ROWS) {
        int r = i - XCH - ECH;
        const float* p = X + (size_t)r * DIM;
        float acc = 0.0f;
        for (int j = 0; j < DIM; j += 4) {
            float4 v = *reinterpret_cast<const float4*>(p + j);
            acc = __fadd_rn(acc, __fmul_rn(v.x, v.x));
            acc = __fadd_rn(acc, __fmul_rn(v.y, v.y));
            acc = __fadd_rn(acc, __fmul_rn(v.z, v.z));
            acc = __fadd_rn(acc, __fmul_rn(v.w, v.w));
        }
        g_xx[r] = acc;
        g_cnt[r] = 0;
    } else if (i < PREP_THREADS) {
        int r = i - XCH - ECH - N_ROWS;
        const float* p = E + (size_t)r * DIM;
        float acc = 0.0f;
        for (int j = 0; j < DIM; j += 4) {
            float4 v = *reinterpret_cast<const float4*>(p + j);
            acc = __fadd_rn(acc, __fmul_rn(v.x, v.x));
            acc = __fadd_rn(acc, __fmul_rn(v.y, v.y));
            acc = __fadd_rn(acc, __fmul_rn(v.z, v.z));
            acc = __fadd_rn(acc, __fmul_rn(v.w, v.w));
        }
        g_ee[r] = acc;
    }
}

// ---------------------------------------------------------------------------
// 2) FP16 tensor GEMM (m16n8k16) with REGISTER double-buffered global loads.
//    2 CTAs/SM. Epilogue: per-row min + margin candidate push.
// ---------------------------------------------------------------------------
__device__ __forceinline__ void mma16(float* c, const uint32_t* a, const uint32_t* b) {
    asm volatile(
        "mma.sync.aligned.m16n8k16.row.col.f32.f16.f16.f32 "
        "{%0,%1,%2,%3}, {%4,%5,%6,%7}, {%8,%9}, {%0,%1,%2,%3};"
        : "+f"(c[0]), "+f"(c[1]), "+f"(c[2]), "+f"(c[3])
        : "r"(a[0]), "r"(a[1]), "r"(a[2]), "r"(a[3]), "r"(b[0]), "r"(b[1]));
}

__global__ __launch_bounds__(256, 2) void gemm_select_kernel() {
    __shared__ __half As[BM * SAH];
    __shared__ __half Bs[BN * SAH];
    __shared__ int   s_min[BM];
    __shared__ float s_xx[BM];
    __shared__ float s_ee[BN];

    int tid = threadIdx.x;
    int lane = tid & 31, wid = tid >> 5;
    int wm = wid >> 2, wn = wid & 3;          // 2 x 4 warp grid, warp tile 64x32
    int n0 = blockIdx.y * BM;
    int c0 = blockIdx.x * BN;

    if (tid < BM) { s_min[tid] = 0x7f7fffff; s_xx[tid] = g_xx[n0 + tid]; }
    if (tid < BN) s_ee[tid] = g_ee[c0 + tid];

    float acc[4][4][4];
#pragma unroll
    for (int mt = 0; mt < 4; ++mt)
#pragma unroll
        for (int nt = 0; nt < 4; ++nt)
#pragma unroll
            for (int h = 0; h < 4; ++h) acc[mt][nt][h] = 0.0f;

    // load roles: chunk (tid + 256*i): row = row0 + 32*i, seg constant
    int row0 = tid >> 3, seg = tid & 7;
    const __half* gx = g_X16 + (size_t)(n0 + row0) * DIM + seg * 8;
    const __half* ge = g_E16 + (size_t)(c0 + row0) * DIM + seg * 8;

    uint4 pa[4], pb[4];
#pragma unroll
    for (int i = 0; i < 4; ++i) {             // prefetch kt=0
        pa[i] = *reinterpret_cast<const uint4*>(gx + (size_t)i * 32 * DIM);
        pb[i] = *reinterpret_cast<const uint4*>(ge + (size_t)i * 32 * DIM);
    }

    for (int kt = 0; kt < KT; ++kt) {
#pragma unroll
        for (int i = 0; i < 4; ++i) {
            *reinterpret_cast<uint4*>(As + (row0 + 32 * i) * SAH + seg * 8) = pa[i];
            *reinterpret_cast<uint4*>(Bs + (row0 + 32 * i) * SAH + seg * 8) = pb[i];
        }
        __syncthreads();
        if (kt + 1 < KT) {                     // prefetch next tile during compute
#pragma unroll
            for (int i = 0; i < 4; ++i) {
                pa[i] = *reinterpret_cast<const uint4*>(gx + (kt + 1) * BKH + (size_t)i * 32 * DIM);
                pb[i] = *reinterpret_cast<const uint4*>(ge + (kt + 1) * BKH + (size_t)i * 32 * DIM);
            }
        }
#pragma unroll
        for (int s = 0; s < 4; ++s) {          // 4 k16 steps per tile
            int kb = s * 16 + (lane & 3) * 2;
            uint32_t af[4][4], bf[4][2];
#pragma unroll
            for (int mt = 0; mt < 4; ++mt) {
                int r = wm * 64 + mt * 16 + (lane >> 2);
                af[mt][0] = *reinterpret_cast<const uint32_t*>(As + r * SAH + kb);
                af[mt][1] = *reinterpret_cast<const uint32_t*>(As + (r + 8) * SAH + kb);
                af[mt][2] = *reinterpret_cast<const uint32_t*>(As + r * SAH + kb + 8);
                af[mt][3] = *reinterpret_cast<const uint32_t*>(As + (r + 8) * SAH + kb + 8);
            }
#pragma unroll
            for (int nt = 0; nt < 4; ++nt) {
                int cc = wn * 32 + nt * 8 + (lane >> 2);
                bf[nt][0] = *reinterpret_cast<const uint32_t*>(Bs + cc * SAH + kb);
                bf[nt][1] = *reinterpret_cast<const uint32_t*>(Bs + cc * SAH + kb + 8);
            }
#pragma unroll
            for (int mt = 0; mt < 4; ++mt)
#pragma unroll
                for (int nt = 0; nt < 4; ++nt)
                    mma16(acc[mt][nt], af[mt], bf[nt]);
        }
        __syncthreads();                       // smem consumed; safe to STS next
    }

    // Epilogue: approx distances, per-row block min, margin push.
#pragma unroll
    for (int mt = 0; mt < 4; ++mt) {
#pragma unroll
        for (int rr = 0; rr < 2; ++rr) {
            int rowb = wm * 64 + mt * 16 + (lane >> 2) + 8 * rr;
            float xxv = s_xx[rowb];
            float dmin_t = CUDART_INF_F;
#pragma unroll
            for (int nt = 0; nt < 4; ++nt) {
#pragma unroll
                for (int cc = 0; cc < 2; ++cc) {
                    int h = rr * 2 + cc;
                    int colb = wn * 32 + nt * 8 + 2 * (lane & 3) + cc;
                    float d = (xxv + s_ee[colb]) - acc[mt][nt][h] * DSCALE;
                    acc[mt][nt][h] = d;
                    dmin_t = fminf(dmin_t, d);
                }
            }
            atomicMin(&s_min[rowb], __float_as_int(dmin_t));  // distances > 0
        }
    }
    __syncthreads();
#pragma unroll
    for (int mt = 0; mt < 4; ++mt) {
#pragma unroll
        for (int rr = 0; rr < 2; ++rr) {
            int rowb = wm * 64 + mt * 16 + (lane >> 2) + 8 * rr;
            float thr = __int_as_float(s_min[rowb]) + MARGIN;
#pragma unroll
            for (int nt = 0; nt < 4; ++nt) {
#pragma unroll
                for (int cc = 0; cc < 2; ++cc) {
                    int h = rr * 2 + cc;
                    float d = acc[mt][nt][h];
                    if (d <= thr) {
                        int gr = n0 + rowb;
                        int gc = c0 + wn * 32 + nt * 8 + 2 * (lane & 3) + cc;
                        int slot = atomicAdd(&g_cnt[gr], 1);
                        if (slot < CAND_CAP)
                            g_cand[gr * CAND_CAP + slot] =
                                make_uint2(__float_as_uint(d), (unsigned)gc);
                    }
                }
            }
        }
    }
}

// ---------------------------------------------------------------------------
// 3) Refine v2: warp-per-candidate exact fp32 re-eval. Winner = min over
//    packed (de_bits, idx) keys == first-index-on-tie argmin.
// ---------------------------------------------------------------------------
__global__ __launch_bounds__(256) void refine_kernel(
        const float* __restrict__ X, const float* __restrict__ E) {
    int row = blockIdx.x;
    int tid = threadIdx.x;
    int lane = tid & 31, wid = tid >> 5;

    __shared__ float s_red[8];
    __shared__ int   s_fc[64];
    __shared__ int   s_m;
    __shared__ unsigned long long s_best[8];

    int n = g_cnt[row];
    if (n > CAND_CAP) n = CAND_CAP;
    if (tid == 0) s_m = 0;

    // global approx min over candidates
    float m = CUDART_INF_F;
    for (int base = 0; base < n; base += 256) {
        int t = base + tid;
        if (t < n) m = fminf(m, __uint_as_float(g_cand[row * CAND_CAP + t].x));
    }
#pragma unroll
    for (int o = 16; o > 0; o >>= 1) m = fminf(m, __shfl_xor_sync(0xffffffffu, m, o));
    if (lane == 0) s_red[wid] = m;
    __syncthreads();
    if (tid == 0) {
        float mm = s_red[0];
#pragma unroll
        for (int w = 1; w < 8; ++w) mm = fminf(mm, s_red[w]);
        s_red[0] = mm;
    }
    __syncthreads();
    float thr = s_red[0] + MARGIN;
    for (int base = 0; base < n; base += 256) {
        int t = base + tid;
        if (t < n) {
            uint2 u = g_cand[row * CAND_CAP + t];
            if (__uint_as_float(u.x) <= thr) {
                int s = atomicAdd(&s_m, 1);
                if (s < 64) s_fc[s] = (int)u.y;
            }
        }
    }
    __syncthreads();
    int m2 = s_m < 64 ? s_m : 64;

    // lane-strided X row in registers (coalesced)
    const float* xr = X + (size_t)row * DIM;
    float xv[16];
#pragma unroll
    for (int t = 0; t < 16; ++t) xv[t] = xr[lane + 32 * t];

    float xxv = g_xx[row];
    unsigned long long best = ~0ull;
    for (int j = wid; j < m2; j += 8) {
        int cc = s_fc[j];
        const float* er = E + (size_t)cc * DIM;
        float a = 0.0f;
#pragma unroll
        for (int t = 0; t < 16; ++t) a = __fmaf_rn(xv[t], er[lane + 32 * t], a);
#pragma unroll
        for (int o = 16; o > 0; o >>= 1) a += __shfl_xor_sync(0xffffffffu, a, o);
        float de = __fadd_rn(__fadd_rn(xxv, g_ee[cc]), __fmul_rn(-2.0f, a));
        unsigned long long key =
            ((unsigned long long)__float_as_uint(de) << 32) | (unsigned)cc;
        if (key < best) best = key;
    }
    if (lane == 0) s_best[wid] = best;
    __syncthreads();
    if (tid == 0) {
        unsigned long long b = s_best[0];
#pragma unroll
        for (int w = 1; w < 8; ++w) if (s_best[w] < b) b = s_best[w];
        g_idx[row] = (int)(b & 0xffffffffu);
    }
}

// ---------------------------------------------------------------------------
// 4) Outputs: gather + STE + per-row double partials of (q-x)^2.
// ---------------------------------------------------------------------------
__global__ __launch_bounds__(128) void output_kernel(
        const float* __restrict__ X, const float* __restrict__ E,
        float* __restrict__ out,
        int off_qste, int off_q, int off_idx, long out_size) {
    int row = blockIdx.x;
    __shared__ double red[128];
    int idx = g_idx[row];

    if (threadIdx.x == 0 && off_idx >= 0) {
        long p = (long)off_idx + row;
        if (p < out_size) out[p] = (float)idx;
    }

    double acc = 0.0;
#pragma unroll
    for (int u = 0; u < 4; ++u) {
        int cdim = threadIdx.x + u * 128;
        float ev = E[(size_t)idx * DIM + cdim];
        float xv = X[(size_t)row * DIM + cdim];
        float diff = __fadd_rn(ev, -xv);
        float qs   = __fadd_rn(xv, diff);
        long el = (long)row * DIM + cdim;
        if (off_qste >= 0) { long p = off_qste + el; if (p < out_size) out[p] = qs; }
        if (off_q    >= 0) { long p = off_q    + el; if (p < out_size) out[p] = ev; }
        acc += (double)__fmul_rn(diff, diff);
    }
    red[threadIdx.x] = acc;
    __syncthreads();
    for (int s = 64; s > 0; s >>= 1) {
        if (threadIdx.x < s) red[threadIdx.x] += red[threadIdx.x + s];
        __syncthreads();
    }
    if (threadIdx.x == 0) g_partial[row] = red[0];
}

__global__ __launch_bounds__(512) void loss_kernel(
        float* __restrict__ out, int off_ql, int off_el, long out_size) {
    __shared__ double red[512];
    double a = 0.0;
    int base = threadIdx.x * 32;
    for (int j = 0; j < 32; ++j) a += g_partial[base + j];
    red[threadIdx.x] = a;
    __syncthreads();
    for (int s = 256; s > 0; s >>= 1) {
        if (threadIdx.x < s) red[threadIdx.x] += red[threadIdx.x + s];
        __syncthreads();
    }
    if (threadIdx.x == 0) {
        float l = (float)(red[0] / (double)NELEM);
        if (off_ql >= 0 && off_ql < out_size) out[off_ql] = l;
        if (off_el >= 0 && off_el < out_size) out[off_el] = l;
    }
}

// ---------------------------------------------------------------------------
extern "C" void kernel_launch(void* const* d_in, const int* in_sizes, int n_in,
                              void* d_out, int out_size) {
    const float* X = (const float*)d_in[0];
    const float* E = (const float*)d_in[1];
    float* out = (float*)d_out;

    int off_qste = -1, off_q = -1, off_ql = -1, off_el = -1, off_idx = -1;
    const int NE = NELEM;
    if (out_size >= 2 * NE + 2 + N_ROWS) {
        off_qste = 0; off_q = NE; off_ql = 2 * NE; off_el = 2 * NE + 1; off_idx = 2 * NE + 2;
    } else if (out_size == NE)          { off_qste = 0; }
    else if (out_size == 2 * NE)        { off_qste = 0; off_q = NE; }
    else if (out_size == 2 * NE + 2)    { off_qste = 0; off_q = NE; off_ql = 2 * NE; off_el = 2 * NE + 1; }
    else if (out_size == N_ROWS)        { off_idx = 0; }
    else {
        off_qste = 0; off_q = NE; off_ql = 2 * NE; off_el = 2 * NE + 1; off_idx = 2 * NE + 2;
    }
    long osz = (long)out_size;

    prep_kernel<<<(PREP_THREADS + 255) / 256, 256>>>(X, E);

    dim3 grid(K_CODES / BN, N_ROWS / BM);   // 64 x 128
    gemm_select_kernel<<<grid, 256>>>();

    refine_kernel<<<N_ROWS, 256>>>(X, E);
    output_kernel<<<N_ROWS, 128>>>(X, E, out, off_qste, off_q, off_idx, osz);
    loss_kernel<<<1, 512>>>(out, off_ql, off_el, osz);
}